// round 2
// baseline (speedup 1.0000x reference)
#include <cuda_runtime.h>

#define T_LEN   512
#define BATCH   2048
#define HID     64
#define NGATE   256          // 4 * HID
#define NB      16           // batches per block
#define THREADS 128

typedef unsigned long long ull;

__device__ __forceinline__ ull pack2(float x, float y) {
    ull r; asm("mov.b64 %0, {%1, %2};" : "=l"(r) : "f"(x), "f"(y)); return r;
}
__device__ __forceinline__ void unpack2(ull v, float& x, float& y) {
    asm("mov.b64 {%0, %1}, %2;" : "=f"(x), "=f"(y) : "l"(v));
}
// Packed f32x2 FMA (sm_10x FFMA2) — IEEE fp32 per lane, 2x FFMA throughput.
__device__ __forceinline__ ull fma2(ull a, ull b, ull c) {
    ull d; asm("fma.rn.f32x2 %0, %1, %2, %3;" : "=l"(d) : "l"(a), "l"(b), "l"(c));
    return d;
}
__device__ __forceinline__ float sigm(float x) {
    float e = __expf(-x);
    return __fdividef(1.0f, 1.0f + e);
}
__device__ __forceinline__ float tanh_fast(float x) {
    float e = __expf(-2.0f * x);
    return __fdividef(2.0f, 1.0f + e) - 1.0f;
}

__global__ __launch_bounds__(THREADS, 1)
void lstm_kernel(const float* __restrict__ x,
                 const float* __restrict__ w_ih,
                 const float* __restrict__ w_hh,
                 const float* __restrict__ b_ih,
                 const float* __restrict__ b_hh,
                 const float* __restrict__ w_fc,
                 const float* __restrict__ b_fc,
                 float* __restrict__ out)
{
    // w_sh: [NGATE][64] floats, 16B-chunk swizzled: float k of row r lives at
    //   r*64 + (((k>>2) ^ (r&7))<<2) + (k&3)
    // -> for fixed chunk c, the 32 lanes (rows tx+32m) hit each of the 8
    //    bank-quads exactly 4 times: optimal 4-phase LDS.128.
    __shared__ __align__(16) float w_sh[NGATE * HID];          // 64 KB
    __shared__ __align__(16) float h_sh[2][NB][HID];           // 8 KB ping-pong

    const int tid = threadIdx.x;
    const int tx  = tid & 31;          // lane: hidden units tx and tx+32
    const int ty  = tid >> 5;          // warp: batch group of 4
    const int b0  = blockIdx.x * NB + ty * 4;
    const int rsw = tx & 7;            // swizzle key (same for all 8 rows of this lane)

    // Stage w_hh [256][64] into swizzled shared
    for (int idx = tid; idx < NGATE * HID; idx += THREADS) {
        int r = idx >> 6, k = idx & 63;
        w_sh[r * 64 + ((((k >> 2) ^ (r & 7)) << 2) | (k & 3))] = w_hh[idx];
    }
    // Zero initial hidden state (buffer 0 only; buffer 1 written at t=0)
    for (int idx = tid; idx < NB * HID; idx += THREADS)
        ((float*)h_sh[0])[idx] = 0.0f;

    // Per-thread weights: gate rows r = tx + 32*m, m=0..7
    // m even -> unit tx, m odd -> unit tx+32; m/2 = gate type (i,f,g,o)
    float wih[8], bias[8];
    #pragma unroll
    for (int m = 0; m < 8; ++m) {
        int r = tx + 32 * m;
        wih[m]  = w_ih[r];             // I == 1
        bias[m] = b_ih[r] + b_hh[r];
    }
    const float wfc0 = w_fc[tx];
    const float wfc1 = w_fc[tx + 32];
    const float bfc  = b_fc[0];

    const float* xp0 = x + (size_t)(b0 + 0) * T_LEN;
    const float* xp1 = x + (size_t)(b0 + 1) * T_LEN;
    const float* xp2 = x + (size_t)(b0 + 2) * T_LEN;
    const float* xp3 = x + (size_t)(b0 + 3) * T_LEN;
    float* op0 = out + (size_t)(b0 + 0) * T_LEN;
    float* op1 = out + (size_t)(b0 + 1) * T_LEN;
    float* op2 = out + (size_t)(b0 + 2) * T_LEN;
    float* op3 = out + (size_t)(b0 + 3) * T_LEN;

    float c[4][2];
    #pragma unroll
    for (int b = 0; b < 4; ++b) { c[b][0] = 0.0f; c[b][1] = 0.0f; }

    // Prefetch x for t=0
    float xv0 = __ldg(xp0), xv1 = __ldg(xp1), xv2 = __ldg(xp2), xv3 = __ldg(xp3);

    __syncthreads();

    for (int t = 0; t < T_LEN; ++t) {
        // Issue next step's x loads early (latency hidden under the k-loop)
        const int tn = (t + 1 < T_LEN) ? t + 1 : t;
        float xn0 = __ldg(xp0 + tn);
        float xn1 = __ldg(xp1 + tn);
        float xn2 = __ldg(xp2 + tn);
        float xn3 = __ldg(xp3 + tn);

        // acc halves: .x accumulates even-k products (+ input/bias), .y odd-k
        ull acc[4][8];
        #pragma unroll
        for (int m = 0; m < 8; ++m) {
            acc[0][m] = pack2(fmaf(xv0, wih[m], bias[m]), 0.0f);
            acc[1][m] = pack2(fmaf(xv1, wih[m], bias[m]), 0.0f);
            acc[2][m] = pack2(fmaf(xv2, wih[m], bias[m]), 0.0f);
            acc[3][m] = pack2(fmaf(xv3, wih[m], bias[m]), 0.0f);
        }

        const float* hcur = h_sh[t & 1][ty * 4];

        // Recurrent matvec over k in chunks of 4 (two f32x2 pairs per chunk)
        #pragma unroll 4
        for (int cc = 0; cc < 16; ++cc) {
            float4 h4_0 = *(const float4*)(hcur + 0 * HID + (cc << 2));
            float4 h4_1 = *(const float4*)(hcur + 1 * HID + (cc << 2));
            float4 h4_2 = *(const float4*)(hcur + 2 * HID + (cc << 2));
            float4 h4_3 = *(const float4*)(hcur + 3 * HID + (cc << 2));
            ull hlo[4], hhi[4];
            hlo[0] = pack2(h4_0.x, h4_0.y); hhi[0] = pack2(h4_0.z, h4_0.w);
            hlo[1] = pack2(h4_1.x, h4_1.y); hhi[1] = pack2(h4_1.z, h4_1.w);
            hlo[2] = pack2(h4_2.x, h4_2.y); hhi[2] = pack2(h4_2.z, h4_2.w);
            hlo[3] = pack2(h4_3.x, h4_3.y); hhi[3] = pack2(h4_3.z, h4_3.w);
            #pragma unroll
            for (int m = 0; m < 8; ++m) {
                int r = tx + 32 * m;
                float4 w4 = *(const float4*)(w_sh + r * 64 + ((cc ^ rsw) << 2));
                ull wlo = pack2(w4.x, w4.y);
                ull whi = pack2(w4.z, w4.w);
                acc[0][m] = fma2(hlo[0], wlo, acc[0][m]);
                acc[1][m] = fma2(hlo[1], wlo, acc[1][m]);
                acc[2][m] = fma2(hlo[2], wlo, acc[2][m]);
                acc[3][m] = fma2(hlo[3], wlo, acc[3][m]);
                acc[0][m] = fma2(hhi[0], whi, acc[0][m]);
                acc[1][m] = fma2(hhi[1], whi, acc[1][m]);
                acc[2][m] = fma2(hhi[2], whi, acc[2][m]);
                acc[3][m] = fma2(hhi[3], whi, acc[3][m]);
            }
        }

        // Gate nonlinearities + state update (PyTorch order i,f,g,o)
        float hnew[4][2];
        #pragma unroll
        for (int b = 0; b < 4; ++b) {
            float gt[8];
            #pragma unroll
            for (int m = 0; m < 8; ++m) {
                float lo, hi;
                unpack2(acc[b][m], lo, hi);
                gt[m] = lo + hi;
            }
            #pragma unroll
            for (int u = 0; u < 2; ++u) {
                float ig = sigm(gt[0 + u]);
                float fg = sigm(gt[2 + u]);
                float gg = tanh_fast(gt[4 + u]);
                float og = sigm(gt[6 + u]);
                float cn = fmaf(fg, c[b][u], ig * gg);
                c[b][u] = cn;
                hnew[b][u] = og * tanh_fast(cn);
            }
        }

        // Write new h into the OTHER buffer (no WAR hazard -> single barrier)
        float* hnxt = h_sh[(t + 1) & 1][ty * 4];
        #pragma unroll
        for (int b = 0; b < 4; ++b) {
            hnxt[b * HID + tx]      = hnew[b][0];
            hnxt[b * HID + tx + 32] = hnew[b][1];
        }

        // Output head: out[b][t] = h . w_fc + b_fc (warp reduction over units)
        float po[4];
        #pragma unroll
        for (int b = 0; b < 4; ++b)
            po[b] = fmaf(hnew[b][0], wfc0, hnew[b][1] * wfc1);
        #pragma unroll
        for (int off = 16; off > 0; off >>= 1) {
            po[0] += __shfl_xor_sync(0xffffffffu, po[0], off);
            po[1] += __shfl_xor_sync(0xffffffffu, po[1], off);
            po[2] += __shfl_xor_sync(0xffffffffu, po[2], off);
            po[3] += __shfl_xor_sync(0xffffffffu, po[3], off);
        }
        if (tx == 0) {
            op0[t] = po[0] + bfc;
            op1[t] = po[1] + bfc;
            op2[t] = po[2] + bfc;
            op3[t] = po[3] + bfc;
        }

        xv0 = xn0; xv1 = xn1; xv2 = xn2; xv3 = xn3;

        __syncthreads();   // new h visible before next step's reads
    }
}

extern "C" void kernel_launch(void* const* d_in, const int* in_sizes, int n_in,
                              void* d_out, int out_size)
{
    const float* x    = (const float*)d_in[0];
    const float* w_ih = (const float*)d_in[1];
    const float* w_hh = (const float*)d_in[2];
    const float* b_ih = (const float*)d_in[3];
    const float* b_hh = (const float*)d_in[4];
    const float* w_fc = (const float*)d_in[5];
    const float* b_fc = (const float*)d_in[6];
    float* out = (float*)d_out;

    lstm_kernel<<<BATCH / NB, THREADS>>>(x, w_ih, w_hh, b_ih, b_hh,
                                         w_fc, b_fc, out);
}